// round 11
// baseline (speedup 1.0000x reference)
#include <cuda_runtime.h>
#include <math.h>

#define NN 50000
#define EE 500000
#define CLAMPV 5.0f

// ---------------- scratch ----------------------------------------------------
__device__ float g_Qh[NN * 128];
__device__ float g_Kh[NN * 128];
__device__ float g_Vh[NN * 128];
__device__ float g_eexp[(size_t)EE * 8];
__device__ float g_denom[NN * 8];
__device__ float g_rowV[NN * 128];

// ---------------- helpers ----------------------------------------------------
__device__ __forceinline__ void red_add_v4(float* addr, float a, float b, float c, float d) {
    asm volatile("red.global.add.v4.f32 [%0], {%1,%2,%3,%4};"
                 :: "l"(addr), "f"(a), "f"(b), "f"(c), "f"(d) : "memory");
}

// ---------------- zero scratch ------------------------------------------------
__global__ void zero_kernel() {
    int stride = gridDim.x * blockDim.x;
    int total = NN * 128 + NN * 8;
    for (int i = blockIdx.x * blockDim.x + threadIdx.x; i < total; i += stride) {
        if (i < NN * 128) g_rowV[i] = 0.f;
        else              g_denom[i - NN * 128] = 0.f;
    }
}

// ---------------- node GEMM (fp32 + register prefetch) ------------------------
__global__ __launch_bounds__(256) void node_gemm(
    const float* __restrict__ x,
    const float* __restrict__ WQ, const float* __restrict__ bQ,
    const float* __restrict__ WK, const float* __restrict__ bK,
    const float* __restrict__ WV, const float* __restrict__ bV,
    float* __restrict__ d_out)
{
    const int which = blockIdx.y;
    const float* W    = (which == 0) ? WQ : (which == 1) ? WK : WV;
    const float* bias = (which == 0) ? bQ : (which == 1) ? bK : bV;
    float* out        = (which == 0) ? g_Qh : (which == 1) ? g_Kh : g_Vh;

    __shared__ float As[64 * 16];
    __shared__ float Bs[16 * 128];

    const int tid = threadIdx.x;
    const int tx = tid & 15, ty = tid >> 4;
    const int m0 = blockIdx.x * 64;

    const int ar = tid >> 2;
    const int ac = (tid & 3) * 4;
    const int brow = tid >> 4;
    const int bcol = (tid & 15) * 8;
    const int mrow = m0 + ar;

    float acc[4][8];
    #pragma unroll
    for (int i = 0; i < 4; i++)
        #pragma unroll
        for (int j = 0; j < 8; j++) acc[i][j] = 0.f;

    float4 av, bv0, bv1;
    // prologue: prefetch chunk 0
    av = make_float4(0.f, 0.f, 0.f, 0.f);
    if (mrow < NN) av = *(const float4*)&x[(size_t)mrow * 128 + ac];
    bv0 = *(const float4*)&W[(size_t)brow * 128 + bcol];
    bv1 = *(const float4*)&W[(size_t)brow * 128 + bcol + 4];

    for (int k0 = 0; k0 < 128; k0 += 16) {
        *(float4*)&As[ar * 16 + ac] = av;
        *(float4*)&Bs[brow * 128 + bcol]     = bv0;
        *(float4*)&Bs[brow * 128 + bcol + 4] = bv1;
        __syncthreads();

        if (k0 + 16 < 128) {   // prefetch next chunk while computing
            const int kn = k0 + 16;
            av = make_float4(0.f, 0.f, 0.f, 0.f);
            if (mrow < NN) av = *(const float4*)&x[(size_t)mrow * 128 + kn + ac];
            bv0 = *(const float4*)&W[(size_t)(kn + brow) * 128 + bcol];
            bv1 = *(const float4*)&W[(size_t)(kn + brow) * 128 + bcol + 4];
        }

        #pragma unroll
        for (int k = 0; k < 16; k++) {
            float a[4], b[8];
            #pragma unroll
            for (int i = 0; i < 4; i++) a[i] = As[(ty * 4 + i) * 16 + k];
            #pragma unroll
            for (int j = 0; j < 8; j++) b[j] = Bs[k * 128 + tx * 8 + j];
            #pragma unroll
            for (int i = 0; i < 4; i++)
                #pragma unroll
                for (int j = 0; j < 8; j++)
                    acc[i][j] = fmaf(a[i], b[j], acc[i][j]);
        }
        __syncthreads();
    }

    #pragma unroll
    for (int i = 0; i < 4; i++) {
        int m = m0 + ty * 4 + i;
        if (m >= NN) continue;
        #pragma unroll
        for (int j = 0; j < 8; j++) {
            int c = tx * 8 + j;
            float v = acc[i][j] + bias[c];
            out[(size_t)m * 128 + c] = v;
            if (which == 0) d_out[(size_t)m * 128 + c] = v;
        }
    }
}

// ---------------- edge GEMM fp32: 64(M) x 256(N), 8x8 microtile ---------------
// R9 proven kernel + register prefetch: LDG(ch+1) issued before compute(ch),
// so global latency is hidden behind the 16 k-step FMA block.
__global__ __launch_bounds__(256) void edge_gemm_f32(
    const float* __restrict__ ea,
    const float* __restrict__ WE, const float* __restrict__ bE,
    const int* __restrict__ edge_index,
    const float* __restrict__ Aw,
    float* __restrict__ d_out)
{
    extern __shared__ float sm[];
    float* As  = sm;            // [64][16]
    float* Bs  = sm + 1024;     // [16][256]
    float* Ex  = sm;            // [64][256] (aliases As/Bs after compute)
    float* AwS = sm + 16384;    // [128]

    const int tid = threadIdx.x;
    const int tx = tid & 31, ty = tid >> 5;   // 32 x 8 thread grid
    const int m0 = blockIdx.x * 64;

    if (tid < 128) AwS[tid] = Aw[tid];

    const int ar = tid >> 2;            // 0..63
    const int ac = (tid & 3) * 4;       // 0,4,8,12
    const int brow = tid >> 4;          // 0..15
    const int bcol = (tid & 15) * 16;   // 0..240
    const int mrow = m0 + ar;

    float acc[8][8];
    #pragma unroll
    for (int i = 0; i < 8; i++)
        #pragma unroll
        for (int j = 0; j < 8; j++) acc[i][j] = 0.f;

    float4 av, bv0, bv1, bv2, bv3;
    // prologue: prefetch chunk 0
    av = make_float4(0.f, 0.f, 0.f, 0.f);
    if (mrow < EE) av = *(const float4*)&ea[(size_t)mrow * 128 + ac];
    {
        const float* wrow = &WE[(size_t)brow * 256 + bcol];
        bv0 = *(const float4*)&wrow[0];
        bv1 = *(const float4*)&wrow[4];
        bv2 = *(const float4*)&wrow[8];
        bv3 = *(const float4*)&wrow[12];
    }

    for (int k0 = 0; k0 < 128; k0 += 16) {
        __syncthreads();   // previous compute done before overwriting smem
        *(float4*)&As[ar * 16 + ac] = av;
        *(float4*)&Bs[brow * 256 + bcol]      = bv0;
        *(float4*)&Bs[brow * 256 + bcol + 4]  = bv1;
        *(float4*)&Bs[brow * 256 + bcol + 8]  = bv2;
        *(float4*)&Bs[brow * 256 + bcol + 12] = bv3;
        __syncthreads();

        if (k0 + 16 < 128) {   // prefetch next chunk; hidden by compute below
            const int kn = k0 + 16;
            av = make_float4(0.f, 0.f, 0.f, 0.f);
            if (mrow < EE) av = *(const float4*)&ea[(size_t)mrow * 128 + kn + ac];
            const float* wrow = &WE[(size_t)(kn + brow) * 256 + bcol];
            bv0 = *(const float4*)&wrow[0];
            bv1 = *(const float4*)&wrow[4];
            bv2 = *(const float4*)&wrow[8];
            bv3 = *(const float4*)&wrow[12];
        }

        #pragma unroll
        for (int k = 0; k < 16; k++) {
            float a[8];
            #pragma unroll
            for (int i = 0; i < 8; i++) a[i] = As[(ty * 8 + i) * 16 + k];   // broadcast
            float4 b0 = *(const float4*)&Bs[k * 256 + tx * 8];
            float4 b1 = *(const float4*)&Bs[k * 256 + tx * 8 + 4];
            const float b[8] = {b0.x, b0.y, b0.z, b0.w, b1.x, b1.y, b1.z, b1.w};
            #pragma unroll
            for (int i = 0; i < 8; i++)
                #pragma unroll
                for (int j = 0; j < 8; j++)
                    acc[i][j] = fmaf(a[i], b[j], acc[i][j]);
        }
    }
    __syncthreads();

    // ---- stash Ex (+bias) ----
    #pragma unroll
    for (int i = 0; i < 8; i++) {
        int r = ty * 8 + i;
        #pragma unroll
        for (int j = 0; j < 8; j++) {
            int c = tx * 8 + j;
            Ex[r * 256 + c] = acc[i][j] + bE[c];
        }
    }
    __syncthreads();

    float* connOut = d_out + (size_t)NN * 128;

    // ---- conn: 64 edges * 8 heads * 16 dims = 8192 values, 32 per thread ----
    for (int idx = tid; idx < 64 * 128; idx += 256) {
        int el  = idx >> 7;
        int rem = idx & 127;
        int gg  = rem >> 4;     // head 0..7
        int d   = rem & 15;
        int e   = m0 + el;
        float x1 = Ex[el * 256 + gg * 32 + d];
        float x2 = Ex[el * 256 + gg * 32 + 16 + d];
        float s2 = x1 * x2;
        float sc2 = copysignf(sqrtf(fabsf(s2)), s2);
        if (e < EE) {
            int src = edge_index[e];
            int dst = edge_index[EE + e];
            float conn = g_Kh[(size_t)src * 128 + gg * 16 + d]
                       + g_Qh[(size_t)dst * 128 + gg * 16 + d] + sc2;
            connOut[(size_t)e * 128 + gg * 16 + d] = conn;
            Ex[el * 256 + gg * 32 + d] = conn;
        }
    }
    __syncthreads();

    // ---- score per (edge, head): 512 tasks, 2 per thread ----
    #pragma unroll
    for (int it = 0; it < 2; it++) {
        int t  = tid + it * 256;
        int el = t >> 3;
        int gg = t & 7;
        int e  = m0 + el;
        if (e < EE) {
            float s = 0.f;
            #pragma unroll
            for (int d = 0; d < 16; d++)
                s = fmaf(Ex[el * 256 + gg * 32 + d], AwS[d * 8 + gg], s);
            s = fminf(fmaxf(s, -CLAMPV), CLAMPV);
            float eev = expf(s);
            g_eexp[(size_t)e * 8 + gg] = eev;
            int dst = edge_index[EE + e];
            atomicAdd(&g_denom[dst * 8 + gg], eev);
        }
    }
}

// ---------------- aggregation: warp per edge (proven) -------------------------
__global__ __launch_bounds__(256) void aggregate(
    const int* __restrict__ edge_index,
    float* __restrict__ d_out)
{
    const int warp = threadIdx.x >> 5;
    const int lane = threadIdx.x & 31;
    const size_t e = (size_t)blockIdx.x * 8 + warp;
    if (e >= EE) return;

    const int src = edge_index[e];
    const int dst = edge_index[EE + e];
    const int h = lane >> 2;

    float den  = g_denom[dst * 8 + h];
    float attn = g_eexp[e * 8 + h] / (den + 1e-16f);

    const float4* Vh4   = (const float4*)g_Vh;
    const float4* conn4 = (const float4*)(d_out + (size_t)NN * 128);
    float4 v = Vh4[(size_t)src * 32 + lane];
    float4 c = conn4[e * 32 + lane];

    float4* out4 = (float4*)d_out;
    float4* row4 = (float4*)g_rowV;
    red_add_v4((float*)&out4[(size_t)dst * 32 + lane], v.x * attn, v.y * attn, v.z * attn, v.w * attn);
    red_add_v4((float*)&row4[(size_t)dst * 32 + lane], c.x * attn, c.y * attn, c.z * attn, c.w * attn);
}

// ---------------- finalize: Vo += rowV @ VeRow per head (proven) --------------
__global__ __launch_bounds__(128) void finalize(
    const float* __restrict__ VeRow,
    float* __restrict__ d_out)
{
    __shared__ float Vs[2048];
    const int tid = threadIdx.x;
    for (int i = tid; i < 2048; i += 128) Vs[i] = VeRow[i];
    __syncthreads();

    const int h = tid >> 4, c = tid & 15;
    const int n0 = blockIdx.x * 32;
    const int nend = (n0 + 32 < NN) ? n0 + 32 : NN;
    for (int n = n0; n < nend; n++) {
        float acc = 0.f;
        #pragma unroll
        for (int d = 0; d < 16; d++)
            acc = fmaf(g_rowV[(size_t)n * 128 + h * 16 + d], Vs[d * 128 + h * 16 + c], acc);
        d_out[(size_t)n * 128 + h * 16 + c] += acc;
    }
}

// ---------------- launch ------------------------------------------------------
#define EDGE_SM ((64 * 256 + 128) * 4)   // Ex + AwS = 66048 bytes

extern "C" void kernel_launch(void* const* d_in, const int* in_sizes, int n_in,
                              void* d_out, int out_size)
{
    const float* x    = (const float*)d_in[0];
    const float* ea   = (const float*)d_in[1];
    const int*   eidx = (const int*)  d_in[2];
    const float* WQ   = (const float*)d_in[3];
    const float* bQ   = (const float*)d_in[4];
    const float* WK   = (const float*)d_in[5];
    const float* bK   = (const float*)d_in[6];
    const float* WE   = (const float*)d_in[7];
    const float* bE   = (const float*)d_in[8];
    const float* WV   = (const float*)d_in[9];
    const float* bV   = (const float*)d_in[10];
    const float* Aw   = (const float*)d_in[11];
    const float* VeRow= (const float*)d_in[12];
    float* out = (float*)d_out;

    static bool attr_set = false;
    if (!attr_set) {
        cudaFuncSetAttribute(edge_gemm_f32,
                             cudaFuncAttributeMaxDynamicSharedMemorySize, EDGE_SM);
        attr_set = true;
    }

    zero_kernel<<<1024, 256>>>();

    dim3 gn((NN + 63) / 64, 3);
    node_gemm<<<gn, 256>>>(x, WQ, bQ, WK, bK, WV, bV, out);

    edge_gemm_f32<<<(EE + 63) / 64, 256, EDGE_SM>>>(ea, WE, bE, eidx, Aw, out);

    aggregate<<<(EE + 7) / 8, 256>>>(eidx, out);

    finalize<<<(NN + 31) / 32, 128>>>(VeRow, out);
}

// round 12
// speedup vs baseline: 1.3441x; 1.3441x over previous
#include <cuda_runtime.h>
#include <math.h>

#define NN 50000
#define EE 500000
#define CLAMPV 5.0f

// ---------------- scratch ----------------------------------------------------
__device__ float g_Qh[NN * 128];
__device__ float g_Kh[NN * 128];
__device__ float g_Vh[NN * 128];
__device__ float g_denom[NN * 8];
__device__ float g_rowV[NN * 128];   // unnormalized sum conn*ex
__device__ float g_accV[NN * 128];   // unnormalized sum Vh[src]*ex

// ---------------- helpers ----------------------------------------------------
__device__ __forceinline__ void red_add_v4(float* addr, float a, float b, float c, float d) {
    asm volatile("red.global.add.v4.f32 [%0], {%1,%2,%3,%4};"
                 :: "l"(addr), "f"(a), "f"(b), "f"(c), "f"(d) : "memory");
}

// ---------------- zero scratch ------------------------------------------------
__global__ void zero_kernel() {
    int stride = gridDim.x * blockDim.x;
    int total = NN * 128 * 2 + NN * 8;
    for (int i = blockIdx.x * blockDim.x + threadIdx.x; i < total; i += stride) {
        if (i < NN * 128)          g_rowV[i] = 0.f;
        else if (i < NN * 128 * 2) g_accV[i - NN * 128] = 0.f;
        else                       g_denom[i - NN * 128 * 2] = 0.f;
    }
}

// ---------------- node GEMM: 128(M) x 128(N), 8x8 microtile -------------------
__global__ __launch_bounds__(256) void node_gemm(
    const float* __restrict__ x,
    const float* __restrict__ WQ, const float* __restrict__ bQ,
    const float* __restrict__ WK, const float* __restrict__ bK,
    const float* __restrict__ WV, const float* __restrict__ bV,
    float* __restrict__ d_out)
{
    const int which = blockIdx.y;
    const float* W    = (which == 0) ? WQ : (which == 1) ? WK : WV;
    const float* bias = (which == 0) ? bQ : (which == 1) ? bK : bV;
    float* out        = (which == 0) ? g_Qh : (which == 1) ? g_Kh : g_Vh;

    __shared__ float As[128 * 16];
    __shared__ float Bs[16 * 128];

    const int tid = threadIdx.x;
    const int tx = tid & 15, ty = tid >> 4;
    const int m0 = blockIdx.x * 128;

    const int ar = tid >> 1;            // 0..127
    const int ac = (tid & 1) * 8;       // 0 or 8
    const int brow = tid >> 4;          // 0..15
    const int bcol = (tid & 15) * 8;    // 0..120
    const int mrow = m0 + ar;

    float acc[8][8];
    #pragma unroll
    for (int i = 0; i < 8; i++)
        #pragma unroll
        for (int j = 0; j < 8; j++) acc[i][j] = 0.f;

    for (int k0 = 0; k0 < 128; k0 += 16) {
        float4 a0 = make_float4(0.f, 0.f, 0.f, 0.f);
        float4 a1 = make_float4(0.f, 0.f, 0.f, 0.f);
        if (mrow < NN) {
            a0 = *(const float4*)&x[(size_t)mrow * 128 + k0 + ac];
            a1 = *(const float4*)&x[(size_t)mrow * 128 + k0 + ac + 4];
        }
        *(float4*)&As[ar * 16 + ac]     = a0;
        *(float4*)&As[ar * 16 + ac + 4] = a1;
        *(float4*)&Bs[brow * 128 + bcol]     = *(const float4*)&W[(size_t)(k0 + brow) * 128 + bcol];
        *(float4*)&Bs[brow * 128 + bcol + 4] = *(const float4*)&W[(size_t)(k0 + brow) * 128 + bcol + 4];
        __syncthreads();
        #pragma unroll
        for (int k = 0; k < 16; k++) {
            float a[8], b[8];
            #pragma unroll
            for (int i = 0; i < 8; i++) a[i] = As[(ty * 8 + i) * 16 + k];
            #pragma unroll
            for (int j = 0; j < 8; j++) b[j] = Bs[k * 128 + tx * 8 + j];
            #pragma unroll
            for (int i = 0; i < 8; i++)
                #pragma unroll
                for (int j = 0; j < 8; j++)
                    acc[i][j] = fmaf(a[i], b[j], acc[i][j]);
        }
        __syncthreads();
    }

    #pragma unroll
    for (int i = 0; i < 8; i++) {
        int m = m0 + ty * 8 + i;
        if (m >= NN) continue;
        #pragma unroll
        for (int j = 0; j < 8; j++) {
            int c = tx * 8 + j;
            float v = acc[i][j] + bias[c];
            out[(size_t)m * 128 + c] = v;
            if (which == 0) d_out[(size_t)m * 128 + c] = v;
        }
    }
}

// ---------------- edge GEMM fp32 (R9 proven) + fused aggregation --------------
// 64(M) x 256(N), 8x8 microtile. Epilogue now also does the scatter-add
// aggregation with UNNORMALIZED weights (ex): denom, accV += Vh*ex,
// rowV += conn*ex. Normalization happens once per node in finalize.
__global__ __launch_bounds__(256) void edge_gemm_f32(
    const float* __restrict__ ea,
    const float* __restrict__ WE, const float* __restrict__ bE,
    const int* __restrict__ edge_index,
    const float* __restrict__ Aw,
    float* __restrict__ d_out)
{
    extern __shared__ float sm[];
    float* As  = sm;            // [64][16]
    float* Bs  = sm + 1024;     // [16][256]
    float* Ex  = sm;            // [64][256] (aliases As/Bs after compute)
    float* AwS = sm + 16384;    // [128]

    const int tid = threadIdx.x;
    const int tx = tid & 31, ty = tid >> 5;   // 32 x 8 thread grid
    const int m0 = blockIdx.x * 64;

    if (tid < 128) AwS[tid] = Aw[tid];

    const int ar = tid >> 2;            // 0..63
    const int ac = (tid & 3) * 4;       // 0,4,8,12
    const int brow = tid >> 4;          // 0..15
    const int bcol = (tid & 15) * 16;   // 0..240

    float acc[8][8];
    #pragma unroll
    for (int i = 0; i < 8; i++)
        #pragma unroll
        for (int j = 0; j < 8; j++) acc[i][j] = 0.f;

    for (int k0 = 0; k0 < 128; k0 += 16) {
        __syncthreads();   // previous compute done before overwriting smem
        float4 av = make_float4(0.f, 0.f, 0.f, 0.f);
        int m = m0 + ar;
        if (m < EE) av = *(const float4*)&ea[(size_t)m * 128 + k0 + ac];
        *(float4*)&As[ar * 16 + ac] = av;
        const float* wrow = &WE[(size_t)(k0 + brow) * 256 + bcol];
        #pragma unroll
        for (int q = 0; q < 4; q++)
            *(float4*)&Bs[brow * 256 + bcol + q * 4] = *(const float4*)&wrow[q * 4];
        __syncthreads();

        #pragma unroll
        for (int k = 0; k < 16; k++) {
            float a[8];
            #pragma unroll
            for (int i = 0; i < 8; i++) a[i] = As[(ty * 8 + i) * 16 + k];   // broadcast
            float4 b0 = *(const float4*)&Bs[k * 256 + tx * 8];
            float4 b1 = *(const float4*)&Bs[k * 256 + tx * 8 + 4];
            const float b[8] = {b0.x, b0.y, b0.z, b0.w, b1.x, b1.y, b1.z, b1.w};
            #pragma unroll
            for (int i = 0; i < 8; i++)
                #pragma unroll
                for (int j = 0; j < 8; j++)
                    acc[i][j] = fmaf(a[i], b[j], acc[i][j]);
        }
    }
    __syncthreads();

    // ---- stash Ex (+bias) ----
    #pragma unroll
    for (int i = 0; i < 8; i++) {
        int r = ty * 8 + i;
        #pragma unroll
        for (int j = 0; j < 8; j++) {
            int c = tx * 8 + j;
            Ex[r * 256 + c] = acc[i][j] + bE[c];
        }
    }
    __syncthreads();

    float* connOut = d_out + (size_t)NN * 128;

    // ---- conn: 64 edges * 8 heads * 16 dims = 8192 values, 32 per thread ----
    for (int idx = tid; idx < 64 * 128; idx += 256) {
        int el  = idx >> 7;
        int rem = idx & 127;
        int gg  = rem >> 4;     // head 0..7
        int d   = rem & 15;
        int e   = m0 + el;
        float x1 = Ex[el * 256 + gg * 32 + d];
        float x2 = Ex[el * 256 + gg * 32 + 16 + d];
        float s2 = x1 * x2;
        float sc2 = copysignf(sqrtf(fabsf(s2)), s2);
        if (e < EE) {
            int src = edge_index[e];
            int dst = edge_index[EE + e];
            float conn = g_Kh[(size_t)src * 128 + gg * 16 + d]
                       + g_Qh[(size_t)dst * 128 + gg * 16 + d] + sc2;
            connOut[(size_t)e * 128 + gg * 16 + d] = conn;
            Ex[el * 256 + gg * 32 + d] = conn;
        }
    }
    __syncthreads();

    // ---- score + fused aggregation per (edge, head): 512 tasks ----
    #pragma unroll
    for (int it = 0; it < 2; it++) {
        int t  = tid + it * 256;
        int el = t >> 3;
        int gg = t & 7;
        int e  = m0 + el;
        if (e < EE) {
            const float* cx = &Ex[el * 256 + gg * 32];
            float s = 0.f;
            #pragma unroll
            for (int d = 0; d < 16; d++)
                s = fmaf(cx[d], AwS[d * 8 + gg], s);
            s = fminf(fmaxf(s, -CLAMPV), CLAMPV);
            float eev = expf(s);
            int src = edge_index[e];
            int dst = edge_index[EE + e];
            atomicAdd(&g_denom[dst * 8 + gg], eev);
            const float4* vv4 = (const float4*)&g_Vh[(size_t)src * 128 + gg * 16];
            float* av = &g_accV[(size_t)dst * 128 + gg * 16];
            float* rv = &g_rowV[(size_t)dst * 128 + gg * 16];
            #pragma unroll
            for (int q = 0; q < 4; q++) {
                float4 v = vv4[q];
                red_add_v4(av + q * 4, v.x * eev, v.y * eev, v.z * eev, v.w * eev);
                red_add_v4(rv + q * 4,
                           cx[q * 4 + 0] * eev, cx[q * 4 + 1] * eev,
                           cx[q * 4 + 2] * eev, cx[q * 4 + 3] * eev);
            }
        }
    }
}

// ---------------- finalize: Vo = Qh + accV/den + (rowV/den)@VeRow -------------
__global__ __launch_bounds__(128) void finalize(
    const float* __restrict__ VeRow,
    float* __restrict__ d_out)
{
    __shared__ float Vs[2048];
    const int tid = threadIdx.x;
    for (int i = tid; i < 2048; i += 128) Vs[i] = VeRow[i];
    __syncthreads();

    const int h = tid >> 4, c = tid & 15;
    const int n0 = blockIdx.x * 32;
    const int nend = (n0 + 32 < NN) ? n0 + 32 : NN;
    for (int n = n0; n < nend; n++) {
        float den = g_denom[n * 8 + h] + 1e-16f;
        float acc = 0.f;
        #pragma unroll
        for (int d = 0; d < 16; d++)
            acc = fmaf(g_rowV[(size_t)n * 128 + h * 16 + d], Vs[d * 128 + h * 16 + c], acc);
        float msg = g_accV[(size_t)n * 128 + h * 16 + c];
        d_out[(size_t)n * 128 + h * 16 + c] += (msg + acc) / den;
    }
}

// ---------------- launch ------------------------------------------------------
#define EDGE_SM ((64 * 256 + 128) * 4)   // Ex + AwS = 66048 bytes

extern "C" void kernel_launch(void* const* d_in, const int* in_sizes, int n_in,
                              void* d_out, int out_size)
{
    const float* x    = (const float*)d_in[0];
    const float* ea   = (const float*)d_in[1];
    const int*   eidx = (const int*)  d_in[2];
    const float* WQ   = (const float*)d_in[3];
    const float* bQ   = (const float*)d_in[4];
    const float* WK   = (const float*)d_in[5];
    const float* bK   = (const float*)d_in[6];
    const float* WE   = (const float*)d_in[7];
    const float* bE   = (const float*)d_in[8];
    const float* WV   = (const float*)d_in[9];
    const float* bV   = (const float*)d_in[10];
    const float* Aw   = (const float*)d_in[11];
    const float* VeRow= (const float*)d_in[12];
    float* out = (float*)d_out;

    static bool attr_set = false;
    if (!attr_set) {
        cudaFuncSetAttribute(edge_gemm_f32,
                             cudaFuncAttributeMaxDynamicSharedMemorySize, EDGE_SM);
        attr_set = true;
    }

    zero_kernel<<<1024, 256>>>();

    dim3 gn((NN + 127) / 128, 3);
    node_gemm<<<gn, 256>>>(x, WQ, bQ, WK, bK, WV, bV, out);

    edge_gemm_f32<<<(EE + 63) / 64, 256, EDGE_SM>>>(ea, WE, bE, eidx, Aw, out);

    finalize<<<(NN + 31) / 32, 128>>>(VeRow, out);
}